// round 15
// baseline (speedup 1.0000x reference)
#include <cuda_runtime.h>

// Inverse 2D DWT, L=2 separable synthesis, stride 2, pad 0 -> per input
// pixel a 2x2 butterfly into the output.
//
// Champion memory pattern (R12): LDG.128 x4 loads, STG.256 .cs x2 stores,
// div-free 32-bit indexing — wrapped in a persistent grid-stride loop
// (grid = 148 SMs x 6 CTAs) to amortize prologue and remove wave
// transitions. Per-iteration access pattern is byte-identical to R12.

__global__ void __launch_bounds__(256)
idwt2_l2_kernel(const float* __restrict__ low,
                const float* __restrict__ highs,
                const float* __restrict__ g0c_p,
                const float* __restrict__ g1c_p,
                const float* __restrict__ g0r_p,
                const float* __restrict__ g1r_p,
                float* __restrict__ out,
                int total)                 // NC * H * W/4 thread-tasks
{
    constexpr int H  = 256, W = 256;
    constexpr int PLANE   = H * W;         // 65536
    constexpr int Wo      = 2 * W;         // 512
    constexpr int OPLANE  = 4 * PLANE;     // 262144
    constexpr int PER_NC  = H * (W / 4);   // 16384 tasks per channel plane

    // Uniform filter taps (broadcast), loaded once per CTA.
    const float a0 = __ldg(&g0c_p[0]), a1 = __ldg(&g0c_p[1]);
    const float b0 = __ldg(&g1c_p[0]), b1 = __ldg(&g1c_p[1]);
    const float c0 = __ldg(&g0r_p[0]), c1 = __ldg(&g0r_p[1]);
    const float d0 = __ldg(&g1r_p[0]), d1 = __ldg(&g1r_p[1]);

    const int stride = gridDim.x * 256;

    for (int idx = blockIdx.x * 256 + threadIdx.x; idx < total; idx += stride) {
        // PER_NC = 16384 = 2^14: div/mod compile to shift/mask.
        const int nc  = idx >> 14;
        const int pos = idx & (PER_NC - 1);
        const int i   = pos >> 6;          // input row
        const int j4  = pos & 63;          // float4 column group

        const unsigned rowoff = (unsigned)i * W + (unsigned)(j4 << 2);
        const unsigned loff   = (unsigned)nc * PLANE + rowoff;
        const unsigned hb     = (unsigned)nc * (3 * PLANE) + rowoff;

        const float4 ll = *reinterpret_cast<const float4*>(low   + loff);
        const float4 lh = *reinterpret_cast<const float4*>(highs + hb);
        const float4 hl = *reinterpret_cast<const float4*>(highs + hb + PLANE);
        const float4 hh = *reinterpret_cast<const float4*>(highs + hb + 2 * PLANE);

        float r0[8], r1[8];

        #define COL(LLC, LHC, HLC, HHC, O)                                    \
        {                                                                     \
            const float A0 = (LLC) * a0 + (LHC) * b0;                         \
            const float B0 = (HLC) * a0 + (HHC) * b0;                         \
            const float A1 = (LLC) * a1 + (LHC) * b1;                         \
            const float B1 = (HLC) * a1 + (HHC) * b1;                         \
            r0[(O)]     = A0 * c0 + B0 * d0;  r0[(O) + 1] = A0 * c1 + B0 * d1;\
            r1[(O)]     = A1 * c0 + B1 * d0;  r1[(O) + 1] = A1 * c1 + B1 * d1;\
        }
        COL(ll.x, lh.x, hl.x, hh.x, 0)
        COL(ll.y, lh.y, hl.y, hh.y, 2)
        COL(ll.z, lh.z, hl.z, hh.z, 4)
        COL(ll.w, lh.w, hl.w, hh.w, 6)
        #undef COL

        const unsigned ooff = (unsigned)nc * OPLANE
                            + (unsigned)(2 * i) * Wo
                            + (unsigned)(j4 << 3);

        asm volatile(
            "st.global.cs.v8.f32 [%0], {%1, %2, %3, %4, %5, %6, %7, %8};"
            :: "l"(out + ooff),
               "f"(r0[0]), "f"(r0[1]), "f"(r0[2]), "f"(r0[3]),
               "f"(r0[4]), "f"(r0[5]), "f"(r0[6]), "f"(r0[7])
            : "memory");
        asm volatile(
            "st.global.cs.v8.f32 [%0], {%1, %2, %3, %4, %5, %6, %7, %8};"
            :: "l"(out + ooff + Wo),
               "f"(r1[0]), "f"(r1[1]), "f"(r1[2]), "f"(r1[3]),
               "f"(r1[4]), "f"(r1[5]), "f"(r1[6]), "f"(r1[7])
            : "memory");
    }
}

extern "C" void kernel_launch(void* const* d_in, const int* in_sizes, int n_in,
                              void* d_out, int out_size)
{
    const float* low   = (const float*)d_in[0];
    const float* highs = (const float*)d_in[1];
    const float* g0c   = (const float*)d_in[2];
    const float* g1c   = (const float*)d_in[3];
    const float* g0r   = (const float*)d_in[4];
    const float* g1r   = (const float*)d_in[5];
    float* out = (float*)d_out;

    const int H = 256, W = 256;
    const int NC = in_sizes[0] / (H * W);
    const int total = NC * H * (W / 4);

    // Persistent: ~6 CTAs/SM on 148 SMs (regs bind around 6 at 40 regs/thread).
    int blocks = 148 * 6;
    const int max_blocks = (total + 255) / 256;
    if (blocks > max_blocks) blocks = max_blocks;

    idwt2_l2_kernel<<<blocks, 256>>>(low, highs, g0c, g1c, g0r, g1r, out, total);
}

// round 16
// speedup vs baseline: 1.0097x; 1.0097x over previous
#include <cuda_runtime.h>

// Inverse 2D DWT, L=2 separable synthesis, stride 2, pad 0 -> per input
// pixel a 2x2 butterfly into the output.
//
// Champion memory pattern (R12): LDG.128 x4 loads, STG.256 .cs x2 stores,
// div-free 32-bit indexing — wrapped in a persistent grid-stride loop
// (grid = 148 SMs x 6 CTAs) to amortize prologue and remove wave
// transitions. Per-iteration access pattern is byte-identical to R12.

__global__ void __launch_bounds__(256)
idwt2_l2_kernel(const float* __restrict__ low,
                const float* __restrict__ highs,
                const float* __restrict__ g0c_p,
                const float* __restrict__ g1c_p,
                const float* __restrict__ g0r_p,
                const float* __restrict__ g1r_p,
                float* __restrict__ out,
                int total)                 // NC * H * W/4 thread-tasks
{
    constexpr int H  = 256, W = 256;
    constexpr int PLANE   = H * W;         // 65536
    constexpr int Wo      = 2 * W;         // 512
    constexpr int OPLANE  = 4 * PLANE;     // 262144
    constexpr int PER_NC  = H * (W / 4);   // 16384 tasks per channel plane

    // Uniform filter taps (broadcast), loaded once per CTA.
    const float a0 = __ldg(&g0c_p[0]), a1 = __ldg(&g0c_p[1]);
    const float b0 = __ldg(&g1c_p[0]), b1 = __ldg(&g1c_p[1]);
    const float c0 = __ldg(&g0r_p[0]), c1 = __ldg(&g0r_p[1]);
    const float d0 = __ldg(&g1r_p[0]), d1 = __ldg(&g1r_p[1]);

    const int stride = gridDim.x * 256;

    for (int idx = blockIdx.x * 256 + threadIdx.x; idx < total; idx += stride) {
        // PER_NC = 16384 = 2^14: div/mod compile to shift/mask.
        const int nc  = idx >> 14;
        const int pos = idx & (PER_NC - 1);
        const int i   = pos >> 6;          // input row
        const int j4  = pos & 63;          // float4 column group

        const unsigned rowoff = (unsigned)i * W + (unsigned)(j4 << 2);
        const unsigned loff   = (unsigned)nc * PLANE + rowoff;
        const unsigned hb     = (unsigned)nc * (3 * PLANE) + rowoff;

        const float4 ll = *reinterpret_cast<const float4*>(low   + loff);
        const float4 lh = *reinterpret_cast<const float4*>(highs + hb);
        const float4 hl = *reinterpret_cast<const float4*>(highs + hb + PLANE);
        const float4 hh = *reinterpret_cast<const float4*>(highs + hb + 2 * PLANE);

        float r0[8], r1[8];

        #define COL(LLC, LHC, HLC, HHC, O)                                    \
        {                                                                     \
            const float A0 = (LLC) * a0 + (LHC) * b0;                         \
            const float B0 = (HLC) * a0 + (HHC) * b0;                         \
            const float A1 = (LLC) * a1 + (LHC) * b1;                         \
            const float B1 = (HLC) * a1 + (HHC) * b1;                         \
            r0[(O)]     = A0 * c0 + B0 * d0;  r0[(O) + 1] = A0 * c1 + B0 * d1;\
            r1[(O)]     = A1 * c0 + B1 * d0;  r1[(O) + 1] = A1 * c1 + B1 * d1;\
        }
        COL(ll.x, lh.x, hl.x, hh.x, 0)
        COL(ll.y, lh.y, hl.y, hh.y, 2)
        COL(ll.z, lh.z, hl.z, hh.z, 4)
        COL(ll.w, lh.w, hl.w, hh.w, 6)
        #undef COL

        const unsigned ooff = (unsigned)nc * OPLANE
                            + (unsigned)(2 * i) * Wo
                            + (unsigned)(j4 << 3);

        asm volatile(
            "st.global.cs.v8.f32 [%0], {%1, %2, %3, %4, %5, %6, %7, %8};"
            :: "l"(out + ooff),
               "f"(r0[0]), "f"(r0[1]), "f"(r0[2]), "f"(r0[3]),
               "f"(r0[4]), "f"(r0[5]), "f"(r0[6]), "f"(r0[7])
            : "memory");
        asm volatile(
            "st.global.cs.v8.f32 [%0], {%1, %2, %3, %4, %5, %6, %7, %8};"
            :: "l"(out + ooff + Wo),
               "f"(r1[0]), "f"(r1[1]), "f"(r1[2]), "f"(r1[3]),
               "f"(r1[4]), "f"(r1[5]), "f"(r1[6]), "f"(r1[7])
            : "memory");
    }
}

extern "C" void kernel_launch(void* const* d_in, const int* in_sizes, int n_in,
                              void* d_out, int out_size)
{
    const float* low   = (const float*)d_in[0];
    const float* highs = (const float*)d_in[1];
    const float* g0c   = (const float*)d_in[2];
    const float* g1c   = (const float*)d_in[3];
    const float* g0r   = (const float*)d_in[4];
    const float* g1r   = (const float*)d_in[5];
    float* out = (float*)d_out;

    const int H = 256, W = 256;
    const int NC = in_sizes[0] / (H * W);
    const int total = NC * H * (W / 4);

    // Persistent: ~6 CTAs/SM on 148 SMs (regs bind around 6 at 40 regs/thread).
    int blocks = 148 * 6;
    const int max_blocks = (total + 255) / 256;
    if (blocks > max_blocks) blocks = max_blocks;

    idwt2_l2_kernel<<<blocks, 256>>>(low, highs, g0c, g1c, g0r, g1r, out, total);
}